// round 1
// baseline (speedup 1.0000x reference)
#include <cuda_runtime.h>
#include <cuda_bf16.h>
#include <math.h>

// Problem dims
#define BB   2
#define SS   1024
#define VV   32000
#define DD   1024
#define RR   256
#define NCC  64
#define NKK  4096
#define KKK  8
#define HH   16
#define LL   4
#define DHH  64
#define BSZ  (BB*SS)          // 2048
#define NCR  (NCC*RR)         // 16384

// ---------------- scratch (device globals; allocation-free) ----------------
__device__ float g_x   [BSZ*DD];         // residual stream
__device__ float g_xln [BSZ*DD];         // layernorm output
__device__ float g_neuT[DD*NCR];         // neurons transposed [D, NC*R]  (64MB)
__device__ float g_T   [(long)BSZ*NCR];  // compress intermediate (134MB)
__device__ float g_rw  [BSZ*NCC];        // router weights
__device__ float g_h   [BSZ*RR];         // compressed rep
__device__ float g_Q   [BSZ*DD];
__device__ float g_K   [BSZ*DD];
__device__ float g_V   [BSZ*DD];
__device__ float g_sc  [(long)BB*HH*SS*SS]; // attention scores (134MB)
__device__ float g_ao  [BSZ*DD];         // attention output (concat heads)
__device__ float g_ms  [BSZ*NKK];        // memory scores
__device__ int   g_ti  [BSZ*KKK];        // topk idx
__device__ float g_tw  [BSZ*KKK];        // topk weights

// ---------------- SGEMM: C[M,N] = alpha * A[M,K] @ op(B) (+C) ----------------
// op(B) = B[K,N] (TB=false, row stride ldb) or B[N,K]^T (TB=true, row stride ldb)
// batched via blockIdx.z with element strides sA/sB/sC.
template<bool TB, bool ACC>
__global__ __launch_bounds__(256)
void sgemm_k(const float* __restrict__ A, const float* __restrict__ B,
             float* __restrict__ C, int M, int N, int K,
             int lda, int ldb, int ldc,
             long sA, long sB, long sC, float alpha)
{
    A += (long)blockIdx.z * sA;
    B += (long)blockIdx.z * sB;
    C += (long)blockIdx.z * sC;

    __shared__ float As[16][128];
    __shared__ float Bs[16][128];

    const int m0 = blockIdx.y * 128;
    const int n0 = blockIdx.x * 128;
    const int t  = threadIdx.x;
    const int tx = t & 15;     // 0..15 -> col group
    const int ty = t >> 4;     // 0..15 -> row group

    float acc[8][8];
#pragma unroll
    for (int i = 0; i < 8; i++)
#pragma unroll
        for (int j = 0; j < 8; j++) acc[i][j] = 0.f;

    for (int k0 = 0; k0 < K; k0 += 16) {
        // ---- load A tile [128 rows][16 k], K is always a multiple of 16 ----
#pragma unroll
        for (int i = 0; i < 2; i++) {
            int f   = t + i * 256;
            int row = f >> 2;
            int c4  = (f & 3) * 4;
            float4 v = make_float4(0.f, 0.f, 0.f, 0.f);
            if (m0 + row < M)
                v = *(const float4*)(A + (long)(m0 + row) * lda + k0 + c4);
            As[c4 + 0][row] = v.x; As[c4 + 1][row] = v.y;
            As[c4 + 2][row] = v.z; As[c4 + 3][row] = v.w;
        }
        // ---- load B tile [16 k][128 n] ----
        if (!TB) {
#pragma unroll
            for (int i = 0; i < 2; i++) {
                int f  = t + i * 256;
                int kr = f >> 5;
                int c4 = (f & 31) * 4;
                float4 v = make_float4(0.f, 0.f, 0.f, 0.f);
                if (n0 + c4 < N)   // N always multiple of 4 in this workload
                    v = *(const float4*)(B + (long)(k0 + kr) * ldb + n0 + c4);
                *(float4*)&Bs[kr][c4] = v;
            }
        } else {
#pragma unroll
            for (int i = 0; i < 2; i++) {
                int f  = t + i * 256;
                int n  = f >> 2;
                int c4 = (f & 3) * 4;
                float4 v = make_float4(0.f, 0.f, 0.f, 0.f);
                if (n0 + n < N)
                    v = *(const float4*)(B + (long)(n0 + n) * ldb + k0 + c4);
                Bs[c4 + 0][n] = v.x; Bs[c4 + 1][n] = v.y;
                Bs[c4 + 2][n] = v.z; Bs[c4 + 3][n] = v.w;
            }
        }
        __syncthreads();

#pragma unroll
        for (int kr = 0; kr < 16; kr++) {
            float a[8], b[8];
            *(float4*)(a)     = *(const float4*)&As[kr][ty * 8];
            *(float4*)(a + 4) = *(const float4*)&As[kr][ty * 8 + 4];
            *(float4*)(b)     = *(const float4*)&Bs[kr][tx * 8];
            *(float4*)(b + 4) = *(const float4*)&Bs[kr][tx * 8 + 4];
#pragma unroll
            for (int i = 0; i < 8; i++)
#pragma unroll
                for (int j = 0; j < 8; j++)
                    acc[i][j] += a[i] * b[j];
        }
        __syncthreads();
    }

#pragma unroll
    for (int i = 0; i < 8; i++) {
        int m = m0 + ty * 8 + i;
        if (m >= M) continue;
#pragma unroll
        for (int j = 0; j < 8; j++) {
            int n = n0 + tx * 8 + j;
            if (n >= N) continue;
            long o = (long)m * ldc + n;
            if (ACC) C[o] = C[o] + alpha * acc[i][j];
            else     C[o] = alpha * acc[i][j];
        }
    }
}

static inline void gemm(bool tb, bool accf,
                        const float* A, const float* B, float* C,
                        int M, int N, int K, int lda, int ldb, int ldc,
                        long sA, long sB, long sC, float alpha, int batch)
{
    dim3 g((N + 127) / 128, (M + 127) / 128, batch);
    if (tb) {
        if (accf) sgemm_k<true , true ><<<g, 256>>>(A, B, C, M, N, K, lda, ldb, ldc, sA, sB, sC, alpha);
        else      sgemm_k<true , false><<<g, 256>>>(A, B, C, M, N, K, lda, ldb, ldc, sA, sB, sC, alpha);
    } else {
        if (accf) sgemm_k<false, true ><<<g, 256>>>(A, B, C, M, N, K, lda, ldb, ldc, sA, sB, sC, alpha);
        else      sgemm_k<false, false><<<g, 256>>>(A, B, C, M, N, K, lda, ldb, ldc, sA, sB, sC, alpha);
    }
}

// ---------------- small kernels ----------------

// neuT[d*NCR + n*R + r] = neurons[(n*D + d)*R + r]; both sides r-contiguous.
__global__ void k_neuT(const float* __restrict__ nn, float* __restrict__ o)
{
    long i = (long)blockIdx.x * 256 + threadIdx.x;   // over D*NC*R = 16.8M
    int r  = (int)(i & (RR - 1));
    long t2 = i >> 8;
    int n  = (int)(t2 & (NCC - 1));
    int d  = (int)(t2 >> 6);
    o[i] = nn[((long)n * DD + d) * RR + r];
}

__global__ void k_embed(const int* __restrict__ tokens, const float* __restrict__ te,
                        const float* __restrict__ pe, float* __restrict__ x)
{
    int s = blockIdx.x;                 // 0..BSZ-1
    int tok = tokens[s];
    int sp  = s & (SS - 1);
    const float* tr = te + (long)tok * DD;
    const float* pr = pe + (long)sp * DD;
    float* xr = x + (long)s * DD;
    for (int d = threadIdx.x; d < DD; d += blockDim.x)
        xr[d] = tr[d] + pr[d];
}

__global__ void k_ln(const float* __restrict__ x, const float* __restrict__ g,
                     const float* __restrict__ b, float* __restrict__ y)
{
    int s = blockIdx.x, t = threadIdx.x;
    __shared__ float row[DD];
    __shared__ float red[256];
    const float* xr = x + (long)s * DD;
    float ls = 0.f;
    for (int d = t; d < DD; d += 256) { float v = xr[d]; row[d] = v; ls += v; }
    red[t] = ls; __syncthreads();
    for (int o = 128; o > 0; o >>= 1) { if (t < o) red[t] += red[t + o]; __syncthreads(); }
    float mean = red[0] * (1.f / DD); __syncthreads();
    float lv = 0.f;
    for (int d = t; d < DD; d += 256) { float dv = row[d] - mean; lv += dv * dv; }
    red[t] = lv; __syncthreads();
    for (int o = 128; o > 0; o >>= 1) { if (t < o) red[t] += red[t + o]; __syncthreads(); }
    float rstd = rsqrtf(red[0] * (1.f / DD) + 1e-5f);
    float* yr = y + (long)s * DD;
    for (int d = t; d < DD; d += 256)
        yr[d] = (row[d] - mean) * rstd * g[d] + b[d];
}

// softmax over rows of length 64 (router weights), in place
__global__ void k_smax64(float* __restrict__ a)
{
    int s = blockIdx.x, t = threadIdx.x;   // block = 64
    __shared__ float m[64];
    float v = a[(long)s * NCC + t];
    m[t] = v; __syncthreads();
    for (int o = 32; o > 0; o >>= 1) { if (t < o) m[t] = fmaxf(m[t], m[t + o]); __syncthreads(); }
    float mx = m[0]; __syncthreads();
    float e = expf(v - mx);
    m[t] = e; __syncthreads();
    for (int o = 32; o > 0; o >>= 1) { if (t < o) m[t] += m[t + o]; __syncthreads(); }
    a[(long)s * NCC + t] = e / m[0];
}

// h[s,r] = sum_n w[s,n] * T[s, n*R + r]
__global__ void k_combine(const float* __restrict__ T, const float* __restrict__ w,
                          float* __restrict__ h)
{
    int s = blockIdx.x, r = threadIdx.x;   // block = 256
    __shared__ float ws[NCC];
    if (r < NCC) ws[r] = w[(long)s * NCC + r];
    __syncthreads();
    const float* Trow = T + (long)s * NCR;
    float acc = 0.f;
#pragma unroll 8
    for (int n = 0; n < NCC; n++)
        acc += ws[n] * Trow[n * RR + r];
    h[(long)s * RR + r] = acc;
}

// causal row softmax over attention scores; rows of length S, zero out k>q
__global__ void k_asmax(float* __restrict__ sc)
{
    int rrow = blockIdx.x;                 // (b*H+h)*S + q
    int q = rrow & (SS - 1);
    int t = threadIdx.x;                   // 256
    __shared__ float row[SS];
    __shared__ float red[256];
    float* p = sc + (long)rrow * SS;
    int len = q + 1;
    float lm = -1e30f;
    for (int d = t; d < len; d += 256) { float v = p[d]; row[d] = v; lm = fmaxf(lm, v); }
    red[t] = lm; __syncthreads();
    for (int o = 128; o > 0; o >>= 1) { if (t < o) red[t] = fmaxf(red[t], red[t + o]); __syncthreads(); }
    float mx = red[0]; __syncthreads();
    float lsum = 0.f;
    for (int d = t; d < len; d += 256) { float e = expf(row[d] - mx); row[d] = e; lsum += e; }
    red[t] = lsum; __syncthreads();
    for (int o = 128; o > 0; o >>= 1) { if (t < o) red[t] += red[t + o]; __syncthreads(); }
    float inv = 1.f / red[0];
    for (int d = t; d < SS; d += 256)
        p[d] = (d < len) ? row[d] * inv : 0.f;
}

// top-8 of 4096 + softmax weights
__global__ void k_topk(const float* __restrict__ sc, int* __restrict__ ti, float* __restrict__ tw)
{
    __shared__ float row[NKK];             // 16KB
    __shared__ float rv[256];
    __shared__ int   ri[256];
    __shared__ float selv[KKK];
    __shared__ int   seli[KKK];
    int s = blockIdx.x, t = threadIdx.x;
    const float* p = sc + (long)s * NKK;
    for (int i = t; i < NKK; i += 256) row[i] = p[i];
    __syncthreads();
    for (int it = 0; it < KKK; it++) {
        float bm = -1e30f; int bi = NKK;
        for (int i = t; i < NKK; i += 256)
            if (row[i] > bm) { bm = row[i]; bi = i; }
        rv[t] = bm; ri[t] = bi; __syncthreads();
        for (int o = 128; o > 0; o >>= 1) {
            if (t < o) {
                if (rv[t + o] > rv[t] || (rv[t + o] == rv[t] && ri[t + o] < ri[t])) {
                    rv[t] = rv[t + o]; ri[t] = ri[t + o];
                }
            }
            __syncthreads();
        }
        if (t == 0) { selv[it] = rv[0]; seli[it] = ri[0]; row[ri[0]] = -1e30f; }
        __syncthreads();
    }
    if (t == 0) {
        float mx = selv[0];
        float e[KKK], sum = 0.f;
#pragma unroll
        for (int j = 0; j < KKK; j++) { e[j] = expf(selv[j] - mx); sum += e[j]; }
        float inv = 1.f / sum;
#pragma unroll
        for (int j = 0; j < KKK; j++) { tw[(long)s * KKK + j] = e[j] * inv; ti[(long)s * KKK + j] = seli[j]; }
    }
}

// x[s,:] += sum_j w[s,j] * kV[idx[s,j], :]
__global__ void k_memout(const float* __restrict__ kV, const int* __restrict__ ti,
                         const float* __restrict__ tw, float* __restrict__ x)
{
    int s = blockIdx.x, t = threadIdx.x;
    __shared__ int   idx[KKK];
    __shared__ float w[KKK];
    if (t < KKK) { idx[t] = ti[(long)s * KKK + t]; w[t] = tw[(long)s * KKK + t]; }
    __syncthreads();
    float* xr = x + (long)s * DD;
    for (int d = t; d < DD; d += 256) {
        float a = xr[d];
#pragma unroll
        for (int j = 0; j < KKK; j++)
            a += w[j] * kV[(long)idx[j] * DD + d];
        xr[d] = a;
    }
}

// ---------------- launch ----------------
extern "C" void kernel_launch(void* const* d_in, const int* in_sizes, int n_in,
                              void* d_out, int out_size)
{
    (void)in_sizes; (void)n_in; (void)out_size;
    const int*   tokens   = (const int*)  d_in[0];
    const float* tok_emb  = (const float*)d_in[1];
    const float* pos_emb  = (const float*)d_in[2];
    const float* neurons  = (const float*)d_in[3];
    const float* kK       = (const float*)d_in[4];
    const float* kV       = (const float*)d_in[5];
    const float* routerQ  = (const float*)d_in[6];
    const float* routerK  = (const float*)d_in[7];
    const float* routerV  = (const float*)d_in[8];
    const float* routerM  = (const float*)d_in[9];
    const float* expQ     = (const float*)d_in[10];
    const float* expK     = (const float*)d_in[11];
    const float* expV     = (const float*)d_in[12];
    const float* expO     = (const float*)d_in[13];
    const float* ln1_g    = (const float*)d_in[14];
    const float* ln1_b    = (const float*)d_in[15];
    const float* ln2_g    = (const float*)d_in[16];
    const float* ln2_b    = (const float*)d_in[17];
    const float* lnf_g    = (const float*)d_in[18];
    const float* lnf_b    = (const float*)d_in[19];
    float* out = (float*)d_out;

    float *px, *pxln, *pneuT, *pT, *prw, *ph, *pQ, *pK, *pV, *psc, *pao, *pms, *ptw;
    int *pti;
    cudaGetSymbolAddress((void**)&px,    g_x);
    cudaGetSymbolAddress((void**)&pxln,  g_xln);
    cudaGetSymbolAddress((void**)&pneuT, g_neuT);
    cudaGetSymbolAddress((void**)&pT,    g_T);
    cudaGetSymbolAddress((void**)&prw,   g_rw);
    cudaGetSymbolAddress((void**)&ph,    g_h);
    cudaGetSymbolAddress((void**)&pQ,    g_Q);
    cudaGetSymbolAddress((void**)&pK,    g_K);
    cudaGetSymbolAddress((void**)&pV,    g_V);
    cudaGetSymbolAddress((void**)&psc,   g_sc);
    cudaGetSymbolAddress((void**)&pao,   g_ao);
    cudaGetSymbolAddress((void**)&pms,   g_ms);
    cudaGetSymbolAddress((void**)&pti,   g_ti);
    cudaGetSymbolAddress((void**)&ptw,   g_tw);

    const float inv_sqrt_dh = 0.125f;   // 1/sqrt(64)
    const float inv_sqrt_r  = 0.0625f;  // 1/sqrt(256)

    // neurons -> [D, NC*R] (once per launch; constant data)
    k_neuT<<<(DD * NCC * RR) / 256, 256>>>(neurons, pneuT);
    // embeddings
    k_embed<<<BSZ, 256>>>(tokens, tok_emb, pos_emb, px);

    for (int l = 0; l < LL; l++) {
        const float* rQ = routerQ + (long)l * NCC * DD;
        const float* rK = routerK + (long)l * NCC * DD;
        const float* rV = routerV + (long)l * NCC * DD;
        const float* rM = routerM + (long)l * NCC * DD;
        const float* eQ = expQ + (long)l * DD * RR;
        const float* eK = expK + (long)l * DD * RR;
        const float* eV = expV + (long)l * DD * RR;
        const float* eO = expO + (long)l * DD * DD;

        // ---- attention sublayer ----
        k_ln<<<BSZ, 256>>>(px, ln1_g + l * DD, ln1_b + l * DD, pxln);
        // shared compress intermediate (router-independent)
        gemm(false, false, pxln, pneuT, pT, BSZ, NCR, DD, DD, NCR, NCR, 0, 0, 0, 1.f, 1);

        const float* routers[3] = { rQ, rK, rV };
        const float* exps[3]    = { eQ, eK, eV };
        float* dsts[3]          = { pQ, pK, pV };
        for (int c = 0; c < 3; c++) {
            gemm(true, false, pxln, routers[c], prw, BSZ, NCC, DD, DD, DD, NCC, 0, 0, 0, 1.f, 1);
            k_smax64<<<BSZ, 64>>>(prw);
            k_combine<<<BSZ, 256>>>(pT, prw, ph);
            gemm(true, false, ph, exps[c], dsts[c], BSZ, DD, RR, RR, RR, DD, 0, 0, 0, 1.f, 1);
        }

        // scores = Q K^T / 8, batched over heads (one launch per batch b)
        for (int b = 0; b < BB; b++) {
            gemm(true, false,
                 pQ + (long)b * SS * DD, pK + (long)b * SS * DD, psc + (long)b * HH * SS * SS,
                 SS, SS, DHH, DD, DD, SS,
                 DHH, DHH, (long)SS * SS, inv_sqrt_dh, HH);
        }
        k_asmax<<<BB * HH * SS, 256>>>(psc);
        // out = P @ V
        for (int b = 0; b < BB; b++) {
            gemm(false, false,
                 psc + (long)b * HH * SS * SS, pV + (long)b * SS * DD, pao + (long)b * SS * DD,
                 SS, DHH, SS, SS, DD, DD,
                 (long)SS * SS, DHH, DHH, 1.f, HH);
        }
        // x += out @ eO^T
        gemm(true, true, pao, eO, px, BSZ, DD, DD, DD, DD, DD, 0, 0, 0, 1.f, 1);

        // ---- memory sublayer ----
        k_ln<<<BSZ, 256>>>(px, ln2_g + l * DD, ln2_b + l * DD, pxln);
        gemm(false, false, pxln, pneuT, pT, BSZ, NCR, DD, DD, NCR, NCR, 0, 0, 0, 1.f, 1);
        gemm(true, false, pxln, rM, prw, BSZ, NCC, DD, DD, DD, NCC, 0, 0, 0, 1.f, 1);
        k_smax64<<<BSZ, 64>>>(prw);
        k_combine<<<BSZ, 256>>>(pT, prw, ph);
        // scores vs knowledge keys
        gemm(true, false, ph, kK, pms, BSZ, NKK, RR, RR, RR, NKK, 0, 0, 0, inv_sqrt_r, 1);
        k_topk<<<BSZ, 256>>>(pms, pti, ptw);
        k_memout<<<BSZ, 256>>>(kV, pti, ptw, px);
    }

    // final LN + tied lm head
    k_ln<<<BSZ, 256>>>(px, lnf_g, lnf_b, pxln);
    gemm(true, false, pxln, tok_emb, out, BSZ, VV, DD, DD, DD, VV, 0, 0, 0, 1.f, 1);
}